// round 8
// baseline (speedup 1.0000x reference)
#include <cuda_runtime.h>
#include <math.h>

#define NMODES      6400
#define NB          50            // blocks over modes
#define TPB         128           // threads per block in p1/p3 (NB*TPB = NMODES)
#define NBINS       260           // lifetime bins (0..258)
#define CHUNK       512           // samples per warp-chunk = 32 lanes * U
#define U           16            // accumulators per lane
#define G           64            // mode groups (partial buffers)
#define GQ          16            // groups per quarter (G/4)
#define MAX_SAMPLES 132096
#define MAX_CHUNKS  258
#define TLN         18.0f         // -ln(~1.5e-8) relative amplitude cutoff

// Static scratch (no runtime allocation allowed)
__device__ float4       g_uA[NMODES], g_uB[NMODES];   // unsorted per-mode params
__device__ int          g_Lm[NMODES];                 // lifetime in chunks
__device__ int          g_hist2[NBINS][NB];
__device__ int          g_cnt[MAX_CHUNKS];            // #active modes at chunk c
__device__ float4       g_pA[NMODES], g_pB[NMODES];   // lifetime-sorted params
__device__ float        g_partial[(size_t)G * MAX_SAMPLES];
__device__ unsigned int g_maxbits;

__device__ __forceinline__ float softplusf(float x) {
    return (x > 20.f) ? x : log1pf(expf(x));
}

// 2pi split for Cody-Waite (compile-time constants)
#define INV2PI 0.15915494309189535f
#define P2_0   6.28125f
#define P2_1   ((float)(6.283185307179586476925 - 6.28125))
#define P2_2   ((float)(6.283185307179586476925 - 6.28125 \
                        - (double)(float)(6.283185307179586476925 - 6.28125)))

// ---------------------------------------------------------------------------
// P1: per-mode params, lifetime, per-block lifetime histogram. 50 x 128.
// ---------------------------------------------------------------------------
__global__ void __launch_bounds__(TPB) p1_kernel(
    const float* mu_raw, const float* D_raw, const float* T0_raw,
    const float* Ly_raw, const float* xo_raw, const float* yo_raw, int nchunks)
{
    __shared__ int sh_hist[NBINS];
    int tid = threadIdx.x, b = blockIdx.x;
    for (int i = tid; i < NBINS; i += TPB) sh_hist[i] = 0;
    if (b == 0 && tid == 0) g_maxbits = 0u;
    __syncthreads();

    int m = b * TPB + tid;

    const float PI    = 3.14159265358979323846f;
    const float LX    = 0.5f;
    const float Kf    = 1.0f / 44100.0f;
    const float MAXOM = (float)(20000.0 * M_PI);
    const float MINOM = (float)(40.0 * M_PI);
    const float ALPHA = (float)(3.0 * 2.302585092994045684 / 6.0);
    const float BETA  = (float)(3.0 * 2.302585092994045684
                                / ((2.0 * M_PI * 500.0) * (2.0 * M_PI * 500.0))
                                * (1.0 - 1.0 / 6.0));

    float mu = softplusf(mu_raw[0]) + 1e-4f;
    float Dm = softplusf(D_raw[0])  + 1e-4f;
    float T0 = softplusf(T0_raw[0]) + 1e-4f;
    float Ly = 1.1f + (4.0f - 1.1f) * ((tanhf(Ly_raw[0]) + 1.0f) * 0.5f);
    float xo = 0.49f * LX + (1.0f - 0.49f) * LX * ((tanhf(xo_raw[0]) + 1.0f) * 0.5f);
    float yo = 0.51f * Ly + (1.0f - 0.51f) * Ly * ((tanhf(yo_raw[0]) + 1.0f) * 0.5f);
    float xi = 0.1f * LX;
    float yi = 0.1f * Ly;

    float Mf = (float)(m / 80 + 1);
    float Nf = (float)(m % 80 + 1);

    float a1 = Mf * PI / LX;
    float a2 = Nf * PI / Ly;
    float g1 = a1 * a1 + a2 * a2;
    float om2 = T0 * g1 + Dm * g1 * g1;
    float omega = sqrtf(fmaxf(om2, 0.f));
    bool valid = (omega <= MAXOM) && (omega >= MINOM);

    float in_w  = cosf(xi * PI * Mf / LX) * cosf(yi * PI * Nf / Ly);
    float out_w = cosf(xo * PI * Mf / LX) * cosf(yo * PI * Nf / Ly);
    float sigma = ALPHA + BETA * omega * omega;
    float msf   = 0.25f * mu * LX * Ly;
    float theta = omega * Kf;
    float denom = sinf(theta) + 1e-8f;
    float sigK  = sigma * Kf;

    // s[n] = C * r^n * sin(n*theta), r = exp(-sigma*K)
    float Cf = out_w * in_w * (Kf * Kf) / (msf * denom);

    int L = 0;
    float c1f = 0.f, c2f = 0.f, rinv32f = 0.f, cs32f = 0.f, sn32f = 0.f;
    if (valid) {
        // 32*theta is an exact fp32 product (exponent shift)
        float x  = 32.f * theta;
        float k  = rintf(x * INV2PI);
        float rr = fmaf(-k, P2_0, x);
        rr = fmaf(-k, P2_1, rr);
        rr = fmaf(-k, P2_2, rr);
        float c32 = cosf(rr);
        float s32 = sinf(rr);
        float r32 = expf(-32.f * sigK);
        c1f     = 2.f * r32 * c32;
        c2f     = r32 * r32;
        rinv32f = 1.f / r32;
        cs32f   = c32;
        sn32f   = s32;
        float lc = TLN / (sigK * (float)CHUNK);
        int   Li = (lc >= (float)nchunks) ? nchunks : ((int)lc + 1);
        L = (Li > nchunks) ? nchunks : Li;
        if (L < 1) L = 1;
    }

    g_uA[m] = make_float4(theta, -sigK, c1f, c2f);
    g_uB[m] = make_float4(rinv32f, cs32f, sn32f, valid ? Cf : 0.f);
    g_Lm[m] = L;
    atomicAdd(&sh_hist[L], 1);
    __syncthreads();
    for (int i = tid; i < NBINS; i += TPB) g_hist2[i][b] = sh_hist[i];
}

// ---------------------------------------------------------------------------
// P3: every block recomputes bin offsets from the (lifetime, block)
// histogram (warp shuffle-scan, no serial chain), then scatters its modes.
// Sort: descending lifetime, ascending block, original order within block.
// ---------------------------------------------------------------------------
__global__ void __launch_bounds__(TPB) p3_kernel(int nchunks)
{
    __shared__ int offL[NBINS];   // totals, then exclusive-desc prefix
    __shared__ int preB[NBINS];   // within-bin offset contributed by blocks < b
    __shared__ int shL[TPB];
    int tid = threadIdx.x, b = blockIdx.x;

    for (int i = tid; i < NBINS; i += TPB) {
        int tot = 0, pre = 0;
#pragma unroll
        for (int bb = 0; bb < NB; bb++) {
            int h = g_hist2[i][bb];
            tot += h;
            if (bb < b) pre += h;
        }
        offL[i] = tot;
        preB[i] = pre;
    }
    __syncthreads();

    // exclusive prefix over DESCENDING lifetime, via warp scan (lane0 = top bin)
    if (tid < 32) {
        int carry = 0;
#pragma unroll
        for (int seg = 0; seg < (NBINS + 31) / 32; seg++) {
            int Lb  = NBINS - 1 - (seg * 32 + tid);
            int val = (Lb >= 0) ? offL[Lb] : 0;
            int incl = val;
#pragma unroll
            for (int o = 1; o < 32; o <<= 1) {
                int up = __shfl_up_sync(0xffffffffu, incl, o);
                if (tid >= o) incl += up;
            }
            if (Lb >= 0) offL[Lb] = carry + (incl - val);
            carry += __shfl_sync(0xffffffffu, incl, 31);
        }
    }
    __syncthreads();

    if (b == 0)
        for (int c = tid; c < nchunks; c += TPB) g_cnt[c] = offL[c];

    int m = b * TPB + tid;
    int L = g_Lm[m];
    shL[tid] = L;
    __syncthreads();
    int local = 0;
    for (int i = 0; i < tid; i++) local += (shL[i] == L);
    int rank = offL[L] + preB[L] + local;
    g_pA[rank] = g_uA[m];
    g_pB[rank] = g_uB[m];
}

// ---------------------------------------------------------------------------
// Modal synthesis. One warp = (chunk c, group g), w = c*G + g so blocks have
// uniform work and heavy chunks launch first. Lane l carries samples
// n0+l+32j via TWO independent stride-64 recurrences (even/odd j).
// Seeds: even chain cur0=s[n], prev0=s[n-64]; odd chain cur1=s[n+32],
// prev1=s[n-32]. Exact init via float Dekker + Cody-Waite.
// ---------------------------------------------------------------------------
__global__ void __launch_bounds__(256) modal_kernel(int N, int nchunks)
{
    int w    = (int)((blockIdx.x * blockDim.x + threadIdx.x) >> 5);
    int lane = threadIdx.x & 31;
    int total = nchunks * G;
    if (w >= total) return;
    int c = w / G;
    int g = w % G;
    int n0 = c * CHUNK;

    int cnt  = g_cnt[c];
    int base = (cnt * g) >> 6;          // G == 64
    int end  = (cnt * (g + 1)) >> 6;

    float acc[U];
#pragma unroll
    for (int j = 0; j < U; j++) acc[j] = 0.f;

    float lf  = (float)lane;
    float n0f = (float)n0;

    for (int r = base; r < end; ++r) {
        float4 pa = g_pA[r];
        float4 pb = g_pB[r];
        float theta = pa.x, msigK = pa.y, c1 = pa.z, c2 = pa.w;
        float rinv32 = pb.x, cs32 = pb.y, sn32 = pb.z, C = pb.w;

        // chunk phase: (n0 * theta) mod 2pi, exact product + 3-term reduction
        float p  = n0f * theta;
        float e  = fmaf(n0f, theta, -p);
        float k  = rintf(p * INV2PI);
        float rr = fmaf(-k, P2_0, p);
        rr = fmaf(-k, P2_1, rr);
        rr = fmaf(-k, P2_2, rr);
        float psi = rr + e;

        // per-lane phase and amplitude
        float a  = fmaf(lf, theta, psi);
        float k2 = rintf(a * INV2PI);
        a = fmaf(-k2, P2_0, a);
        a = fmaf(-k2, P2_1, a);
        float s, co;
        __sincosf(a, &s, &co);
        float Ae = C * __expf(msigK * (n0f + lf));

        // rotation terms for -32 and -64 steps
        float cs64   = fmaf(2.f * cs32, cs32, -1.f);   // cos(64*theta)
        float sn64   = 2.f * sn32 * cs32;              // sin(64*theta)
        float rinv64 = rinv32 * rinv32;

        float cur0  = Ae * s;                                      // s[n]
        float prev1 = (Ae * rinv32) * fmaf(s, cs32, -co * sn32);   // s[n-32]
        float prev0 = (Ae * rinv64) * fmaf(s, cs64, -co * sn64);   // s[n-64]
        float cur1  = fmaf(c1, cur0, -(c2 * prev1));               // s[n+32]

        // stride-64 coefficients: 2 r^64 cos(64th) = c1^2 - 2 c2 ; r^128 = c2^2
        float c1q = fmaf(c1, c1, -(c2 + c2));
        float c2q = c2 * c2;

#pragma unroll
        for (int jj = 0; jj < U / 2; jj++) {
            acc[2 * jj]     += cur0;
            acc[2 * jj + 1] += cur1;
            float n0x = fmaf(c1q, cur0, -(c2q * prev0));
            float n1x = fmaf(c1q, cur1, -(c2q * prev1));
            prev0 = cur0; cur0 = n0x;
            prev1 = cur1; cur1 = n1x;
        }
    }

    float* dst = g_partial + (size_t)g * MAX_SAMPLES + n0 + lane;
#pragma unroll
    for (int j = 0; j < U; j++) {
        int n = n0 + 32 * j + lane;
        if (n < N) dst[32 * j] = acc[j];
    }
}

// ---------------------------------------------------------------------------
// Reduce: block = 64 float4-samples (x) * 4 group-quarters (y). Each thread
// sums GQ=16 of the 64 partial buffers for its float4 (16 independent
// LDG.128 -> high MLP), then a fixed-order smem combine: (q0+q1)+(q2+q3).
// Grid = ceil(N/4/64) = 173 blocks -> full SM coverage. Deterministic.
// ---------------------------------------------------------------------------
__global__ void __launch_bounds__(256) reduce_kernel(float* out, int N)
{
    __shared__ float4 sh[4][64];
    int x = threadIdx.x;          // 0..63  sample slot
    int y = threadIdx.y;          // 0..3   group quarter
    int s4 = blockIdx.x * 64 + x;
    int n  = s4 * 4;

    float4 v = make_float4(0.f, 0.f, 0.f, 0.f);
    if (n < N) {
        const float* basep = g_partial + (size_t)y * GQ * MAX_SAMPLES;
        if (n + 3 < N) {
#pragma unroll
            for (int g = 0; g < GQ; g++) {
                const float4 p = *(const float4*)(basep + (size_t)g * MAX_SAMPLES + n);
                v.x += p.x; v.y += p.y; v.z += p.z; v.w += p.w;
            }
        } else {
            for (int t = n; t < N; ++t) {
                float s = 0.f;
#pragma unroll
                for (int g = 0; g < GQ; g++)
                    s += basep[(size_t)g * MAX_SAMPLES + t];
                if (t == n)     v.x = s;
                else if (t == n + 1) v.y = s;
                else if (t == n + 2) v.z = s;
                else                 v.w = s;
            }
        }
    }
    sh[y][x] = v;
    __syncthreads();

    float am = 0.f;
    if (y == 0 && n < N) {
        float4 a = sh[0][x], bq = sh[1][x], cq = sh[2][x], d = sh[3][x];
        float4 r;
        r.x = (a.x + bq.x) + (cq.x + d.x);
        r.y = (a.y + bq.y) + (cq.y + d.y);
        r.z = (a.z + bq.z) + (cq.z + d.z);
        r.w = (a.w + bq.w) + (cq.w + d.w);
        if (n + 3 < N) {
            *(float4*)(out + n) = r;
            am = fmaxf(fmaxf(fabsf(r.x), fabsf(r.y)), fmaxf(fabsf(r.z), fabsf(r.w)));
        } else {
            float rv[4] = { r.x, r.y, r.z, r.w };
            for (int t = n; t < N; ++t) {
                out[t] = rv[t - n];
                am = fmaxf(am, fabsf(rv[t - n]));
            }
        }
    }

#pragma unroll
    for (int o = 16; o; o >>= 1)
        am = fmaxf(am, __shfl_xor_sync(0xffffffffu, am, o));
    __shared__ float wmax[8];
    int tid = threadIdx.y * 64 + threadIdx.x;
    int wr = tid >> 5;
    if ((tid & 31) == 0) wmax[wr] = am;
    __syncthreads();
    if (tid == 0) {
        float bm = wmax[0];
#pragma unroll
        for (int i = 1; i < 8; i++) bm = fmaxf(bm, wmax[i]);
        atomicMax(&g_maxbits, __float_as_uint(bm));   // abs vals >= 0: int-monotonic
    }
}

__global__ void __launch_bounds__(256) norm_kernel(float* out, int N)
{
    int i4 = blockIdx.x * blockDim.x + threadIdx.x;
    int n  = i4 * 4;
    float inv = 1.0f / (__uint_as_float(g_maxbits) + 1e-8f);
    if (n + 3 < N) {
        float4 v = *(const float4*)(out + n);
        v.x *= inv; v.y *= inv; v.z *= inv; v.w *= inv;
        *(float4*)(out + n) = v;
    } else if (n < N) {
        for (int t = n; t < N; ++t) out[t] *= inv;
    }
}

// ---------------------------------------------------------------------------
extern "C" void kernel_launch(void* const* d_in, const int* in_sizes, int n_in,
                              void* d_out, int out_size)
{
    const float* mu_raw = (const float*)d_in[0];
    const float* D_raw  = (const float*)d_in[1];
    const float* T0_raw = (const float*)d_in[2];
    const float* Ly_raw = (const float*)d_in[3];
    const float* xo_raw = (const float*)d_in[4];
    const float* yo_raw = (const float*)d_in[5];

    int N = out_size;
    if (N > MAX_SAMPLES) N = MAX_SAMPLES;
    int nchunks = (N + CHUNK - 1) / CHUNK;

    p1_kernel<<<NB, TPB>>>(mu_raw, D_raw, T0_raw, Ly_raw, xo_raw, yo_raw, nchunks);
    p3_kernel<<<NB, TPB>>>(nchunks);

    int total_warps = nchunks * G;
    int blocks = (total_warps * 32 + 255) / 256;
    modal_kernel<<<blocks, 256>>>(N, nchunks);

    int n4 = (N + 3) / 4;
    dim3 rblock(64, 4);
    int rgrid = (n4 + 63) / 64;
    reduce_kernel<<<rgrid, rblock>>>((float*)d_out, N);
    int nb2 = (n4 + 255) / 256;
    norm_kernel<<<nb2, 256>>>((float*)d_out, N);
}

// round 9
// speedup vs baseline: 1.1704x; 1.1704x over previous
#include <cuda_runtime.h>
#include <math.h>

#define NMODES      6400
#define NB          50            // blocks over modes
#define TPB         128           // threads per block in p1/p3 (NB*TPB = NMODES)
#define NBINS       260           // lifetime bins (0..258)
#define CHUNK       512           // samples per warp-chunk = 32 lanes * U
#define U           16            // accumulators per lane
#define G           64            // mode groups (warp granularity)
#define GR          8             // partial buffers (one per 8-group octet)
#define MAX_SAMPLES 132096
#define MAX_CHUNKS  258
#define TLN         18.0f         // -ln(~1.5e-8) relative amplitude cutoff

// Static scratch (no runtime allocation allowed)
__device__ float4       g_uA[NMODES], g_uB[NMODES];   // unsorted per-mode params
__device__ int          g_Lm[NMODES];                 // lifetime in chunks
__device__ int          g_hist2[NBINS][NB];
__device__ int          g_cnt[MAX_CHUNKS];            // #active modes at chunk c
__device__ float4       g_pA[NMODES], g_pB[NMODES];   // lifetime-sorted params
__device__ float        g_partial[(size_t)GR * MAX_SAMPLES];
__device__ unsigned int g_maxbits;

__device__ __forceinline__ float softplusf(float x) {
    return (x > 20.f) ? x : log1pf(expf(x));
}

// 2pi split for Cody-Waite (compile-time constants)
#define INV2PI 0.15915494309189535f
#define P2_0   6.28125f
#define P2_1   ((float)(6.283185307179586476925 - 6.28125))
#define P2_2   ((float)(6.283185307179586476925 - 6.28125 \
                        - (double)(float)(6.283185307179586476925 - 6.28125)))

// ---------------------------------------------------------------------------
// P1: per-mode params, lifetime, per-block lifetime histogram. 50 x 128.
// ---------------------------------------------------------------------------
__global__ void __launch_bounds__(TPB) p1_kernel(
    const float* mu_raw, const float* D_raw, const float* T0_raw,
    const float* Ly_raw, const float* xo_raw, const float* yo_raw, int nchunks)
{
    __shared__ int sh_hist[NBINS];
    int tid = threadIdx.x, b = blockIdx.x;
    for (int i = tid; i < NBINS; i += TPB) sh_hist[i] = 0;
    if (b == 0 && tid == 0) g_maxbits = 0u;
    __syncthreads();

    int m = b * TPB + tid;

    const float PI    = 3.14159265358979323846f;
    const float LX    = 0.5f;
    const float Kf    = 1.0f / 44100.0f;
    const float MAXOM = (float)(20000.0 * M_PI);
    const float MINOM = (float)(40.0 * M_PI);
    const float ALPHA = (float)(3.0 * 2.302585092994045684 / 6.0);
    const float BETA  = (float)(3.0 * 2.302585092994045684
                                / ((2.0 * M_PI * 500.0) * (2.0 * M_PI * 500.0))
                                * (1.0 - 1.0 / 6.0));

    float mu = softplusf(mu_raw[0]) + 1e-4f;
    float Dm = softplusf(D_raw[0])  + 1e-4f;
    float T0 = softplusf(T0_raw[0]) + 1e-4f;
    float Ly = 1.1f + (4.0f - 1.1f) * ((tanhf(Ly_raw[0]) + 1.0f) * 0.5f);
    float xo = 0.49f * LX + (1.0f - 0.49f) * LX * ((tanhf(xo_raw[0]) + 1.0f) * 0.5f);
    float yo = 0.51f * Ly + (1.0f - 0.51f) * Ly * ((tanhf(yo_raw[0]) + 1.0f) * 0.5f);
    float xi = 0.1f * LX;
    float yi = 0.1f * Ly;

    float Mf = (float)(m / 80 + 1);
    float Nf = (float)(m % 80 + 1);

    float a1 = Mf * PI / LX;
    float a2 = Nf * PI / Ly;
    float g1 = a1 * a1 + a2 * a2;
    float om2 = T0 * g1 + Dm * g1 * g1;
    float omega = sqrtf(fmaxf(om2, 0.f));
    bool valid = (omega <= MAXOM) && (omega >= MINOM);

    float in_w  = cosf(xi * PI * Mf / LX) * cosf(yi * PI * Nf / Ly);
    float out_w = cosf(xo * PI * Mf / LX) * cosf(yo * PI * Nf / Ly);
    float sigma = ALPHA + BETA * omega * omega;
    float msf   = 0.25f * mu * LX * Ly;
    float theta = omega * Kf;
    float denom = sinf(theta) + 1e-8f;
    float sigK  = sigma * Kf;

    // s[n] = C * r^n * sin(n*theta), r = exp(-sigma*K)
    float Cf = out_w * in_w * (Kf * Kf) / (msf * denom);

    int L = 0;
    float c1f = 0.f, c2f = 0.f, rinv32f = 0.f, cs32f = 0.f, sn32f = 0.f;
    if (valid) {
        // 32*theta is an exact fp32 product (exponent shift)
        float x  = 32.f * theta;
        float k  = rintf(x * INV2PI);
        float rr = fmaf(-k, P2_0, x);
        rr = fmaf(-k, P2_1, rr);
        rr = fmaf(-k, P2_2, rr);
        float c32 = cosf(rr);
        float s32 = sinf(rr);
        float r32 = expf(-32.f * sigK);
        c1f     = 2.f * r32 * c32;
        c2f     = r32 * r32;
        rinv32f = 1.f / r32;
        cs32f   = c32;
        sn32f   = s32;
        float lc = TLN / (sigK * (float)CHUNK);
        int   Li = (lc >= (float)nchunks) ? nchunks : ((int)lc + 1);
        L = (Li > nchunks) ? nchunks : Li;
        if (L < 1) L = 1;
    }

    g_uA[m] = make_float4(theta, -sigK, c1f, c2f);
    g_uB[m] = make_float4(rinv32f, cs32f, sn32f, valid ? Cf : 0.f);
    g_Lm[m] = L;
    atomicAdd(&sh_hist[L], 1);
    __syncthreads();
    for (int i = tid; i < NBINS; i += TPB) g_hist2[i][b] = sh_hist[i];
}

// ---------------------------------------------------------------------------
// P3: every block recomputes bin offsets from the (lifetime, block)
// histogram (warp shuffle-scan, no serial chain), then scatters its modes.
// Sort: descending lifetime, ascending block, original order within block.
// ---------------------------------------------------------------------------
__global__ void __launch_bounds__(TPB) p3_kernel(int nchunks)
{
    __shared__ int offL[NBINS];   // totals, then exclusive-desc prefix
    __shared__ int preB[NBINS];   // within-bin offset contributed by blocks < b
    __shared__ int shL[TPB];
    int tid = threadIdx.x, b = blockIdx.x;

    for (int i = tid; i < NBINS; i += TPB) {
        int tot = 0, pre = 0;
#pragma unroll
        for (int bb = 0; bb < NB; bb++) {
            int h = g_hist2[i][bb];
            tot += h;
            if (bb < b) pre += h;
        }
        offL[i] = tot;
        preB[i] = pre;
    }
    __syncthreads();

    // exclusive prefix over DESCENDING lifetime, via warp scan (lane0 = top bin)
    if (tid < 32) {
        int carry = 0;
#pragma unroll
        for (int seg = 0; seg < (NBINS + 31) / 32; seg++) {
            int Lb  = NBINS - 1 - (seg * 32 + tid);
            int val = (Lb >= 0) ? offL[Lb] : 0;
            int incl = val;
#pragma unroll
            for (int o = 1; o < 32; o <<= 1) {
                int up = __shfl_up_sync(0xffffffffu, incl, o);
                if (tid >= o) incl += up;
            }
            if (Lb >= 0) offL[Lb] = carry + (incl - val);
            carry += __shfl_sync(0xffffffffu, incl, 31);
        }
    }
    __syncthreads();

    if (b == 0)
        for (int c = tid; c < nchunks; c += TPB) g_cnt[c] = offL[c];

    int m = b * TPB + tid;
    int L = g_Lm[m];
    shL[tid] = L;
    __syncthreads();
    int local = 0;
    for (int i = 0; i < tid; i++) local += (shL[i] == L);
    int rank = offL[L] + preB[L] + local;
    g_pA[rank] = g_uA[m];
    g_pB[rank] = g_uB[m];
}

// ---------------------------------------------------------------------------
// Modal synthesis. Block = 8 warps = 8 consecutive groups of ONE chunk:
// block B -> chunk c = B/8, octet q = B%8, warp wid -> group g = q*8+wid.
// Each warp runs its contiguous rank range with two independent stride-64
// recurrences (exact seeds via float Dekker + Cody-Waite), then the block
// combines its 8 warps through smem IN FIXED ORDER (g ascending — identical
// summation order to the previous 64-buffer scheme) and writes ONE partial
// buffer per octet (GR=8).
// ---------------------------------------------------------------------------
__global__ void __launch_bounds__(256) modal_kernel(int N, int nchunks)
{
    __shared__ float sh[8][CHUNK];   // 16 KB

    int B    = blockIdx.x;
    int wid  = threadIdx.x >> 5;
    int lane = threadIdx.x & 31;
    int c  = B >> 3;                 // 8 blocks per chunk
    int q  = B & 7;                  // octet
    int g  = q * 8 + wid;
    int n0 = c * CHUNK;

    int cnt  = g_cnt[c];
    int base = (cnt * g) >> 6;       // G == 64
    int end  = (cnt * (g + 1)) >> 6;

    float acc[U];
#pragma unroll
    for (int j = 0; j < U; j++) acc[j] = 0.f;

    float lf  = (float)lane;
    float n0f = (float)n0;

    for (int r = base; r < end; ++r) {
        float4 pa = g_pA[r];
        float4 pb = g_pB[r];
        float theta = pa.x, msigK = pa.y, c1 = pa.z, c2 = pa.w;
        float rinv32 = pb.x, cs32 = pb.y, sn32 = pb.z, C = pb.w;

        // chunk phase: (n0 * theta) mod 2pi, exact product + 3-term reduction
        float p  = n0f * theta;
        float e  = fmaf(n0f, theta, -p);
        float k  = rintf(p * INV2PI);
        float rr = fmaf(-k, P2_0, p);
        rr = fmaf(-k, P2_1, rr);
        rr = fmaf(-k, P2_2, rr);
        float psi = rr + e;

        // per-lane phase and amplitude
        float a  = fmaf(lf, theta, psi);
        float k2 = rintf(a * INV2PI);
        a = fmaf(-k2, P2_0, a);
        a = fmaf(-k2, P2_1, a);
        float s, co;
        __sincosf(a, &s, &co);
        float Ae = C * __expf(msigK * (n0f + lf));

        // rotation terms for -32 and -64 steps
        float cs64   = fmaf(2.f * cs32, cs32, -1.f);   // cos(64*theta)
        float sn64   = 2.f * sn32 * cs32;              // sin(64*theta)
        float rinv64 = rinv32 * rinv32;

        float cur0  = Ae * s;                                      // s[n]
        float prev1 = (Ae * rinv32) * fmaf(s, cs32, -co * sn32);   // s[n-32]
        float prev0 = (Ae * rinv64) * fmaf(s, cs64, -co * sn64);   // s[n-64]
        float cur1  = fmaf(c1, cur0, -(c2 * prev1));               // s[n+32]

        // stride-64 coefficients: 2 r^64 cos(64th) = c1^2 - 2 c2 ; r^128 = c2^2
        float c1q = fmaf(c1, c1, -(c2 + c2));
        float c2q = c2 * c2;

#pragma unroll
        for (int jj = 0; jj < U / 2; jj++) {
            acc[2 * jj]     += cur0;
            acc[2 * jj + 1] += cur1;
            float n0x = fmaf(c1q, cur0, -(c2q * prev0));
            float n1x = fmaf(c1q, cur1, -(c2q * prev1));
            prev0 = cur0; cur0 = n0x;
            prev1 = cur1; cur1 = n1x;
        }
    }

    // stage per-warp results in smem
#pragma unroll
    for (int j = 0; j < U; j++)
        sh[wid][j * 32 + lane] = acc[j];
    __syncthreads();

    // fixed-order combine (wid 0..7 == group ascending) -> one buffer per octet
    int tid = threadIdx.x;
    float* dst = g_partial + (size_t)q * MAX_SAMPLES;
#pragma unroll
    for (int t = 0; t < 2; t++) {
        int s = tid + t * 256;
        float v = ((sh[0][s] + sh[1][s]) + (sh[2][s] + sh[3][s]))
                + ((sh[4][s] + sh[5][s]) + (sh[6][s] + sh[7][s]));
        int n = n0 + s;
        if (n < N) dst[n] = v;
    }
}

// ---------------------------------------------------------------------------
// Reduce: one thread per sample, 8 independent loads (one latency round),
// write unnormalized output, track peak via atomicMax on float bits.
// ---------------------------------------------------------------------------
__global__ void __launch_bounds__(256) reduce_kernel(float* out, int N)
{
    int n = blockIdx.x * blockDim.x + threadIdx.x;
    float v = 0.f;
    if (n < N) {
#pragma unroll
        for (int g = 0; g < GR; g++)
            v += g_partial[(size_t)g * MAX_SAMPLES + n];
        out[n] = v;
    }
    float am = (n < N) ? fabsf(v) : 0.f;
#pragma unroll
    for (int o = 16; o; o >>= 1)
        am = fmaxf(am, __shfl_xor_sync(0xffffffffu, am, o));
    __shared__ float wmax[8];
    int wr = threadIdx.x >> 5;
    if ((threadIdx.x & 31) == 0) wmax[wr] = am;
    __syncthreads();
    if (threadIdx.x == 0) {
        float bm = wmax[0];
#pragma unroll
        for (int i = 1; i < 8; i++) bm = fmaxf(bm, wmax[i]);
        atomicMax(&g_maxbits, __float_as_uint(bm));   // abs vals >= 0: int-monotonic
    }
}

__global__ void __launch_bounds__(256) norm_kernel(float* out, int N)
{
    int n = blockIdx.x * blockDim.x + threadIdx.x;
    if (n < N) {
        float inv = 1.0f / (__uint_as_float(g_maxbits) + 1e-8f);
        out[n] = out[n] * inv;
    }
}

// ---------------------------------------------------------------------------
extern "C" void kernel_launch(void* const* d_in, const int* in_sizes, int n_in,
                              void* d_out, int out_size)
{
    const float* mu_raw = (const float*)d_in[0];
    const float* D_raw  = (const float*)d_in[1];
    const float* T0_raw = (const float*)d_in[2];
    const float* Ly_raw = (const float*)d_in[3];
    const float* xo_raw = (const float*)d_in[4];
    const float* yo_raw = (const float*)d_in[5];

    int N = out_size;
    if (N > MAX_SAMPLES) N = MAX_SAMPLES;
    int nchunks = (N + CHUNK - 1) / CHUNK;

    p1_kernel<<<NB, TPB>>>(mu_raw, D_raw, T0_raw, Ly_raw, xo_raw, yo_raw, nchunks);
    p3_kernel<<<NB, TPB>>>(nchunks);

    int blocks = nchunks * (G / 8);       // 8 warps (one octet) per block
    modal_kernel<<<blocks, 256>>>(N, nchunks);

    int rb = (N + 255) / 256;
    reduce_kernel<<<rb, 256>>>((float*)d_out, N);
    norm_kernel<<<rb, 256>>>((float*)d_out, N);
}

// round 11
// speedup vs baseline: 1.5467x; 1.3215x over previous
#include <cuda_runtime.h>
#include <math.h>

#define NMODES      6400
#define NB          50            // blocks over modes
#define TPB         128           // threads per block in p1/p3 (NB*TPB = NMODES)
#define NWARP       (TPB / 32)
#define NBINS       260           // lifetime bins (0..258)
#define CHUNK       512           // samples per warp-chunk = 32 lanes * U
#define U           16            // accumulators per lane
#define G           64            // mode groups (warp granularity)
#define GR          8             // partial buffers (one per 8-group octet)
#define MAX_SAMPLES 132096
#define MAX_CHUNKS  258
#define TLN         18.0f         // -ln(~1.5e-8) relative amplitude cutoff
#define RB          148           // reduce blocks: 1/SM, co-resident

// Static scratch (no runtime allocation allowed)
__device__ float4       g_uA[NMODES], g_uB[NMODES];   // unsorted per-mode params
__device__ int          g_Lm[NMODES];                 // lifetime in chunks
__device__ int          g_hist2[NBINS][NB];
__device__ int          g_cnt[MAX_CHUNKS];            // #active modes at chunk c
__device__ float4       g_pA[NMODES], g_pB[NMODES];   // lifetime-sorted params
__device__ float        g_partial[(size_t)GR * MAX_SAMPLES];
__device__ unsigned int g_maxbits;
__device__ unsigned int g_bar = 0u;                   // monotonic barrier counter

__device__ __forceinline__ float softplusf(float x) {
    return (x > 20.f) ? x : log1pf(expf(x));
}

// 2pi split for Cody-Waite (compile-time constants)
#define INV2PI 0.15915494309189535f
#define P2_0   6.28125f
#define P2_1   ((float)(6.283185307179586476925 - 6.28125))
#define P2_2   ((float)(6.283185307179586476925 - 6.28125 \
                        - (double)(float)(6.283185307179586476925 - 6.28125)))

// ---------------------------------------------------------------------------
// P1: per-mode params, lifetime, per-block lifetime histogram. 50 x 128.
// ---------------------------------------------------------------------------
__global__ void __launch_bounds__(TPB) p1_kernel(
    const float* mu_raw, const float* D_raw, const float* T0_raw,
    const float* Ly_raw, const float* xo_raw, const float* yo_raw, int nchunks)
{
    __shared__ int sh_hist[NBINS];
    int tid = threadIdx.x, b = blockIdx.x;
    for (int i = tid; i < NBINS; i += TPB) sh_hist[i] = 0;
    if (b == 0 && tid == 0) g_maxbits = 0u;
    __syncthreads();

    int m = b * TPB + tid;

    const float PI    = 3.14159265358979323846f;
    const float LX    = 0.5f;
    const float Kf    = 1.0f / 44100.0f;
    const float MAXOM = (float)(20000.0 * M_PI);
    const float MINOM = (float)(40.0 * M_PI);
    const float ALPHA = (float)(3.0 * 2.302585092994045684 / 6.0);
    const float BETA  = (float)(3.0 * 2.302585092994045684
                                / ((2.0 * M_PI * 500.0) * (2.0 * M_PI * 500.0))
                                * (1.0 - 1.0 / 6.0));

    float mu = softplusf(mu_raw[0]) + 1e-4f;
    float Dm = softplusf(D_raw[0])  + 1e-4f;
    float T0 = softplusf(T0_raw[0]) + 1e-4f;
    float Ly = 1.1f + (4.0f - 1.1f) * ((tanhf(Ly_raw[0]) + 1.0f) * 0.5f);
    float xo = 0.49f * LX + (1.0f - 0.49f) * LX * ((tanhf(xo_raw[0]) + 1.0f) * 0.5f);
    float yo = 0.51f * Ly + (1.0f - 0.51f) * Ly * ((tanhf(yo_raw[0]) + 1.0f) * 0.5f);
    float xi = 0.1f * LX;
    float yi = 0.1f * Ly;

    float Mf = (float)(m / 80 + 1);
    float Nf = (float)(m % 80 + 1);

    float a1 = Mf * PI / LX;
    float a2 = Nf * PI / Ly;
    float g1 = a1 * a1 + a2 * a2;
    float om2 = T0 * g1 + Dm * g1 * g1;
    float omega = sqrtf(fmaxf(om2, 0.f));
    bool valid = (omega <= MAXOM) && (omega >= MINOM);

    float in_w  = cosf(xi * PI * Mf / LX) * cosf(yi * PI * Nf / Ly);
    float out_w = cosf(xo * PI * Mf / LX) * cosf(yo * PI * Nf / Ly);
    float sigma = ALPHA + BETA * omega * omega;
    float msf   = 0.25f * mu * LX * Ly;
    float theta = omega * Kf;
    float denom = sinf(theta) + 1e-8f;
    float sigK  = sigma * Kf;

    // s[n] = C * r^n * sin(n*theta), r = exp(-sigma*K)
    float Cf = out_w * in_w * (Kf * Kf) / (msf * denom);

    int L = 0;
    float c1f = 0.f, c2f = 0.f, rinv32f = 0.f, cs32f = 0.f, sn32f = 0.f;
    if (valid) {
        // 32*theta is an exact fp32 product (exponent shift)
        float x  = 32.f * theta;
        float k  = rintf(x * INV2PI);
        float rr = fmaf(-k, P2_0, x);
        rr = fmaf(-k, P2_1, rr);
        rr = fmaf(-k, P2_2, rr);
        float c32 = cosf(rr);
        float s32 = sinf(rr);
        float r32 = expf(-32.f * sigK);
        c1f     = 2.f * r32 * c32;
        c2f     = r32 * r32;
        rinv32f = 1.f / r32;
        cs32f   = c32;
        sn32f   = s32;
        float lc = TLN / (sigK * (float)CHUNK);
        int   Li = (lc >= (float)nchunks) ? nchunks : ((int)lc + 1);
        L = (Li > nchunks) ? nchunks : Li;
        if (L < 1) L = 1;
    }

    g_uA[m] = make_float4(theta, -sigK, c1f, c2f);
    g_uB[m] = make_float4(rinv32f, cs32f, sn32f, valid ? Cf : 0.f);
    g_Lm[m] = L;
    atomicAdd(&sh_hist[L], 1);
    __syncthreads();
    for (int i = tid; i < NBINS; i += TPB) g_hist2[i][b] = sh_hist[i];
}

// ---------------------------------------------------------------------------
// P3: every block recomputes bin offsets (warp shuffle-scan), then scatters
// its modes. Within-block rank via __match_any + per-warp bin counts (no
// O(tid) serial smem loop).
// Sort: descending lifetime, ascending block, original order within block.
// ---------------------------------------------------------------------------
__global__ void __launch_bounds__(TPB) p3_kernel(int nchunks)
{
    __shared__ int offL[NBINS];          // totals, then exclusive-desc prefix
    __shared__ int preB[NBINS];          // contribution of blocks < b in bin
    __shared__ int wcnt[NWARP][NBINS];   // per-warp per-bin counts
    int tid = threadIdx.x, b = blockIdx.x;
    int lane = tid & 31, w = tid >> 5;

    for (int i = tid; i < NWARP * NBINS; i += TPB)
        ((int*)wcnt)[i] = 0;

    for (int i = tid; i < NBINS; i += TPB) {
        int tot = 0, pre = 0;
#pragma unroll
        for (int bb = 0; bb < NB; bb++) {
            int h = g_hist2[i][bb];
            tot += h;
            if (bb < b) pre += h;
        }
        offL[i] = tot;
        preB[i] = pre;
    }
    __syncthreads();

    // exclusive prefix over DESCENDING lifetime, via warp scan (lane0 = top bin)
    if (tid < 32) {
        int carry = 0;
#pragma unroll
        for (int seg = 0; seg < (NBINS + 31) / 32; seg++) {
            int Lb  = NBINS - 1 - (seg * 32 + tid);
            int val = (Lb >= 0) ? offL[Lb] : 0;
            int incl = val;
#pragma unroll
            for (int o = 1; o < 32; o <<= 1) {
                int up = __shfl_up_sync(0xffffffffu, incl, o);
                if (tid >= o) incl += up;
            }
            if (Lb >= 0) offL[Lb] = carry + (incl - val);
            carry += __shfl_sync(0xffffffffu, incl, 31);
        }
    }

    int m = b * TPB + tid;
    int L = g_Lm[m];
    unsigned mask   = __match_any_sync(0xffffffffu, L);
    int      inwarp = __popc(mask & ((1u << lane) - 1u));
    int      leader = __ffs(mask) - 1;
    if (lane == leader) wcnt[w][L] = __popc(mask);
    __syncthreads();

    if (b == 0)
        for (int c = tid; c < nchunks; c += TPB) g_cnt[c] = offL[c];

    int local = inwarp;
#pragma unroll
    for (int w2 = 0; w2 < NWARP; w2++)
        if (w2 < w) local += wcnt[w2][L];
    int rank = offL[L] + preB[L] + local;
    g_pA[rank] = g_uA[m];
    g_pB[rank] = g_uB[m];
}

// ---------------------------------------------------------------------------
// Modal synthesis. Block = 8 warps = 8 consecutive groups of ONE chunk:
// block B -> chunk c = B/8, octet q = B%8, warp wid -> group g = q*8+wid.
// Two independent stride-64 recurrences per mode (exact seeds via float
// Dekker + Cody-Waite); fixed-order smem combine -> one buffer per octet.
// ---------------------------------------------------------------------------
__global__ void __launch_bounds__(256) modal_kernel(int N, int nchunks)
{
    __shared__ float sh[8][CHUNK];   // 16 KB

    int B    = blockIdx.x;
    int wid  = threadIdx.x >> 5;
    int lane = threadIdx.x & 31;
    int c  = B >> 3;                 // 8 blocks per chunk
    int q  = B & 7;                  // octet
    int g  = q * 8 + wid;
    int n0 = c * CHUNK;

    int cnt  = g_cnt[c];
    int base = (cnt * g) >> 6;       // G == 64
    int end  = (cnt * (g + 1)) >> 6;

    float acc[U];
#pragma unroll
    for (int j = 0; j < U; j++) acc[j] = 0.f;

    float lf  = (float)lane;
    float n0f = (float)n0;

    for (int r = base; r < end; ++r) {
        float4 pa = g_pA[r];
        float4 pb = g_pB[r];
        float theta = pa.x, msigK = pa.y, c1 = pa.z, c2 = pa.w;
        float rinv32 = pb.x, cs32 = pb.y, sn32 = pb.z, C = pb.w;

        // chunk phase: (n0 * theta) mod 2pi, exact product + 3-term reduction
        float p  = n0f * theta;
        float e  = fmaf(n0f, theta, -p);
        float k  = rintf(p * INV2PI);
        float rr = fmaf(-k, P2_0, p);
        rr = fmaf(-k, P2_1, rr);
        rr = fmaf(-k, P2_2, rr);
        float psi = rr + e;

        // per-lane phase and amplitude
        float a  = fmaf(lf, theta, psi);
        float k2 = rintf(a * INV2PI);
        a = fmaf(-k2, P2_0, a);
        a = fmaf(-k2, P2_1, a);
        float s, co;
        __sincosf(a, &s, &co);
        float Ae = C * __expf(msigK * (n0f + lf));

        // rotation terms for -32 and -64 steps
        float cs64   = fmaf(2.f * cs32, cs32, -1.f);   // cos(64*theta)
        float sn64   = 2.f * sn32 * cs32;              // sin(64*theta)
        float rinv64 = rinv32 * rinv32;

        float cur0  = Ae * s;                                      // s[n]
        float prev1 = (Ae * rinv32) * fmaf(s, cs32, -co * sn32);   // s[n-32]
        float prev0 = (Ae * rinv64) * fmaf(s, cs64, -co * sn64);   // s[n-64]
        float cur1  = fmaf(c1, cur0, -(c2 * prev1));               // s[n+32]

        // stride-64 coefficients: 2 r^64 cos(64th) = c1^2 - 2 c2 ; r^128 = c2^2
        float c1q = fmaf(c1, c1, -(c2 + c2));
        float c2q = c2 * c2;

#pragma unroll
        for (int jj = 0; jj < U / 2; jj++) {
            acc[2 * jj]     += cur0;
            acc[2 * jj + 1] += cur1;
            float n0x = fmaf(c1q, cur0, -(c2q * prev0));
            float n1x = fmaf(c1q, cur1, -(c2q * prev1));
            prev0 = cur0; cur0 = n0x;
            prev1 = cur1; cur1 = n1x;
        }
    }

    // stage per-warp results in smem
#pragma unroll
    for (int j = 0; j < U; j++)
        sh[wid][j * 32 + lane] = acc[j];
    __syncthreads();

    // fixed-order combine (wid 0..7 == group ascending) -> one buffer per octet
    int tid = threadIdx.x;
    float* dst = g_partial + (size_t)q * MAX_SAMPLES;
#pragma unroll
    for (int t = 0; t < 2; t++) {
        int s = tid + t * 256;
        float v = ((sh[0][s] + sh[1][s]) + (sh[2][s] + sh[3][s]))
                + ((sh[4][s] + sh[5][s]) + (sh[6][s] + sh[7][s]));
        int n = n0 + s;
        if (n < N) dst[n] = v;
    }
}

// ---------------------------------------------------------------------------
// Fused reduce + normalize. 148 blocks (1/SM, wave-1 deterministic placement
// => co-resident => spin barrier is safe). Sums stay in NAMED REGISTERS
// (compile-time indexing, no spill). Nothing is stored to global before the
// barrier, so the fence is cheap. Peak via atomicMax on float bits
// (order-independent -> deterministic).
// ---------------------------------------------------------------------------
__global__ void __launch_bounds__(256) reduce_norm_kernel(float* out, int N)
{
    const int stride = RB * 256;
    int t0 = blockIdx.x * 256 + threadIdx.x;
    int n1 = t0 + stride, n2 = t0 + 2 * stride, n3 = t0 + 3 * stride;

    float v0 = 0.f, v1 = 0.f, v2 = 0.f, v3 = 0.f;
    if (t0 < N) {
#pragma unroll
        for (int g = 0; g < GR; g++) v0 += g_partial[(size_t)g * MAX_SAMPLES + t0];
    }
    if (n1 < N) {
#pragma unroll
        for (int g = 0; g < GR; g++) v1 += g_partial[(size_t)g * MAX_SAMPLES + n1];
    }
    if (n2 < N) {
#pragma unroll
        for (int g = 0; g < GR; g++) v2 += g_partial[(size_t)g * MAX_SAMPLES + n2];
    }
    if (n3 < N) {
#pragma unroll
        for (int g = 0; g < GR; g++) v3 += g_partial[(size_t)g * MAX_SAMPLES + n3];
    }

    float am = fmaxf(fmaxf(fabsf(v0), fabsf(v1)), fmaxf(fabsf(v2), fabsf(v3)));
#pragma unroll
    for (int o = 16; o; o >>= 1)
        am = fmaxf(am, __shfl_xor_sync(0xffffffffu, am, o));
    __shared__ float wmax[8];
    int wr = threadIdx.x >> 5;
    if ((threadIdx.x & 31) == 0) wmax[wr] = am;
    __syncthreads();

    if (threadIdx.x == 0) {
        float bm = wmax[0];
#pragma unroll
        for (int i = 1; i < 8; i++) bm = fmaxf(bm, wmax[i]);
        atomicMax(&g_maxbits, __float_as_uint(bm));
        __threadfence();   // order atomicMax before counter arrival
        unsigned int old = atomicAdd(&g_bar, 1u);
        unsigned int target = old - (old % RB) + RB;   // monotonic across replays
        while (*(volatile unsigned int*)&g_bar < target) { }
    }
    __syncthreads();

    float inv = 1.0f / (__uint_as_float(__ldcg(&g_maxbits)) + 1e-8f);
    if (t0 < N) out[t0] = v0 * inv;
    if (n1 < N) out[n1] = v1 * inv;
    if (n2 < N) out[n2] = v2 * inv;
    if (n3 < N) out[n3] = v3 * inv;
}

// ---------------------------------------------------------------------------
extern "C" void kernel_launch(void* const* d_in, const int* in_sizes, int n_in,
                              void* d_out, int out_size)
{
    const float* mu_raw = (const float*)d_in[0];
    const float* D_raw  = (const float*)d_in[1];
    const float* T0_raw = (const float*)d_in[2];
    const float* Ly_raw = (const float*)d_in[3];
    const float* xo_raw = (const float*)d_in[4];
    const float* yo_raw = (const float*)d_in[5];

    int N = out_size;
    if (N > MAX_SAMPLES) N = MAX_SAMPLES;
    int nchunks = (N + CHUNK - 1) / CHUNK;

    p1_kernel<<<NB, TPB>>>(mu_raw, D_raw, T0_raw, Ly_raw, xo_raw, yo_raw, nchunks);
    p3_kernel<<<NB, TPB>>>(nchunks);

    int blocks = nchunks * (G / 8);       // 8 warps (one octet) per block
    modal_kernel<<<blocks, 256>>>(N, nchunks);

    reduce_norm_kernel<<<RB, 256>>>((float*)d_out, N);
}